// round 11
// baseline (speedup 1.0000x reference)
#include <cuda_runtime.h>
#include <cstdint>

#define N_ROWS 8192
#define O_COLS 4096
#define K_DIM  4096
#define KWORDS 128

// work split: IMMA handles rows [0, IMMA_ROWS), popcount the rest
#define IMMA_ROWS 2944               // 23 tiles of 128
#define POPC_OFF  IMMA_ROWS          // 5248 rows = 82 tiles of 64

// ---- scratch (device globals; no dynamic allocation allowed) ----
__device__ __align__(16) unsigned xp_g[(size_t)N_ROWS * KWORDS];   // 4 MB packed bits
__device__ __align__(16) unsigned wp_g[(size_t)O_COLS * KWORDS];   // 2 MB
__device__ __align__(16) int8_t   x8_g[(size_t)N_ROWS * K_DIM];    // 33.5 MB int8
__device__ __align__(16) int8_t   w8_g[(size_t)O_COLS * K_DIM];    // 16.8 MB
__device__ float psum_g[N_ROWS];
__device__ float mean_g;

// ============================================================
// helpers
// ============================================================
__device__ __forceinline__ uint32_t smem_u32(const void* p) {
    uint32_t a;
    asm("{ .reg .u64 t; cvta.to.shared.u64 t, %1; cvt.u32.u64 %0, t; }" : "=r"(a) : "l"(p));
    return a;
}
__device__ __forceinline__ void cp16(uint32_t s, const void* g) {
    asm volatile("cp.async.cg.shared.global [%0], [%1], 16;" :: "r"(s), "l"(g) : "memory");
}
__device__ __forceinline__ void cp_commit() { asm volatile("cp.async.commit_group;" ::: "memory"); }
__device__ __forceinline__ void cp_wait2()  { asm volatile("cp.async.wait_group 2;" ::: "memory"); }

#define LDSM_X4(r0, r1, r2, r3, addr) \
    asm volatile("ldmatrix.sync.aligned.m8n8.x4.shared.b16 {%0,%1,%2,%3}, [%4];" \
                 : "=r"(r0), "=r"(r1), "=r"(r2), "=r"(r3) : "r"(addr))
#define LDSM_X2(r0, r1, addr) \
    asm volatile("ldmatrix.sync.aligned.m8n8.x2.shared.b16 {%0,%1}, [%2];" \
                 : "=r"(r0), "=r"(r1) : "r"(addr))
#define IMMA(d, a, b) \
    asm volatile("mma.sync.aligned.m16n8k32.row.col.s32.s8.s8.s32 " \
                 "{%0,%1,%2,%3}, {%4,%5,%6,%7}, {%8,%9}, {%0,%1,%2,%3};" \
                 : "+r"((d)[0]), "+r"((d)[1]), "+r"((d)[2]), "+r"((d)[3]) \
                 : "r"((a)[0]), "r"((a)[1]), "r"((a)[2]), "r"((a)[3]), \
                   "r"((b)[0]), "r"((b)[1]))

__device__ __forceinline__ int8_t s8sign(float v) {
    return (int8_t)((v > 0.f) - (v < 0.f));
}
__device__ __forceinline__ int imad_pack(int hi, int sh, int lo) {
    int r;
    asm("mad.lo.s32 %0, %1, %2, %3;" : "=r"(r) : "r"(hi), "r"(sh), "r"(lo));
    return r;
}

// ============================================================
// fused prep: sign bits + int8 signs (+ |x| sums for x)
// ============================================================
__global__ void pack_x_kernel(const float* __restrict__ x) {
    const int row  = blockIdx.x;
    const int tid  = threadIdx.x;
    const int lane = tid & 31;
    const int warp = tid >> 5;

    const float* xr = x + (size_t)row * K_DIM;
    float s = 0.f;

    #pragma unroll 4
    for (int it = 0; it < 32; it++) {
        const int w = warp * 32 + it;
        const float v = xr[w * 32 + lane];
        s += fabsf(v);
        const unsigned bits = __ballot_sync(0xffffffffu, __float_as_uint(v) >> 31);
        if (lane == 0) xp_g[(size_t)row * KWORDS + w] = bits;
        x8_g[(size_t)row * K_DIM + w * 32 + lane] = s8sign(v);
    }

    __shared__ float red[128];
    red[tid] = s;
    __syncthreads();
    #pragma unroll
    for (int off = 64; off > 0; off >>= 1) {
        if (tid < off) red[tid] += red[tid + off];
        __syncthreads();
    }
    if (tid == 0) psum_g[row] = red[0];
}

__global__ void pack_w_kernel(const float* __restrict__ W) {
    const int row  = blockIdx.x;
    const int tid  = threadIdx.x;
    const int lane = tid & 31;
    const int warp = tid >> 5;

    const float* wr = W + (size_t)row * K_DIM;

    #pragma unroll 4
    for (int it = 0; it < 32; it++) {
        const int w = warp * 32 + it;
        const float v = wr[w * 32 + lane];
        const unsigned bits = __ballot_sync(0xffffffffu, __float_as_uint(v) >> 31);
        if (lane == 0) wp_g[(size_t)row * KWORDS + w] = bits;
        w8_g[(size_t)row * K_DIM + w * 32 + lane] = s8sign(v);
    }
}

__global__ void reduce_mean_kernel() {
    __shared__ float red[1024];
    const int tid = threadIdx.x;
    float s = 0.f;
    for (int i = tid; i < N_ROWS; i += 1024) s += psum_g[i];
    red[tid] = s;
    __syncthreads();
    #pragma unroll
    for (int off = 512; off > 0; off >>= 1) {
        if (tid < off) red[tid] += red[tid + off];
        __syncthreads();
    }
    if (tid == 0) mean_g = red[0] * (1.0f / ((float)N_ROWS * (float)K_DIM));
}

// ============================================================
// IMMA GEMM for rows [0, IMMA_ROWS): CTA 128x64, 256 thr, 4-stage cp.async.
// Small footprint (96KB smem, ~75 regs) so popcount CTAs co-reside per SM.
// ============================================================
#define KB 128
#define NCHUNK (K_DIM / KB)          // 32
#define IM_MT 128
#define IM_NT 64
#define A_ST (IM_MT * KB)            // 16384
#define B_ST (IM_NT * KB)            // 8192
#define ST_BYTES (A_ST + B_ST)       // 24576
#define IM_SMEM (4 * ST_BYTES)       // 98304

__global__ __launch_bounds__(256)
void imma_gemm_kernel(const float* __restrict__ bias, float* __restrict__ out) {
    extern __shared__ __align__(1024) char smem[];
    const uint32_t sb = smem_u32(smem);
    const int tid  = threadIdx.x;
    const int wid  = tid >> 5;
    const int lane = tid & 31;

    const int m0 = blockIdx.y * IM_MT;
    const int n0 = blockIdx.x * IM_NT;
    const int8_t* gA = x8_g + (size_t)m0 * K_DIM;
    const int8_t* gB = w8_g + (size_t)n0 * K_DIM;

    // loaders: A 128 rows x 8 segs -> 4 cp16/thread; B 64 rows x 8 segs -> 2
    const int arow = tid >> 1;                 // 0..127
    const int aseg0 = (tid & 1) * 4;           // 0 or 4
    const int brow = tid >> 2;                 // 0..63
    const int bseg0 = (tid & 3) * 2;           // 0,2,4,6
    uint32_t sA[4], sB[2];
    #pragma unroll
    for (int j = 0; j < 4; j++)
        sA[j] = (uint32_t)arow * 128u + (uint32_t)(((aseg0 + j) ^ (arow & 7)) << 4);
    #pragma unroll
    for (int j = 0; j < 2; j++)
        sB[j] = (uint32_t)brow * 128u + (uint32_t)(((bseg0 + j) ^ (brow & 7)) << 4);

    // compute: 8 warps, 4(m) x 2(n); warp tile 32x32
    const int wm = wid >> 1;                   // 0..3
    const int wn = wid & 1;                    // 0..1
    uint32_t aRow128[2]; int aMask[2];
    #pragma unroll
    for (int am = 0; am < 2; am++) {
        const int r = wm * 32 + am * 16 + (lane & 15);
        aRow128[am] = (uint32_t)r * 128u;
        aMask[am] = r & 7;
    }
    const int aKseg = lane >> 4;
    uint32_t bRow128[4]; int bMask[4];
    #pragma unroll
    for (int bn = 0; bn < 4; bn++) {
        const int r = wn * 32 + bn * 8 + (lane & 7);
        bRow128[bn] = (uint32_t)r * 128u;
        bMask[bn] = r & 7;
    }
    const int bKseg = (lane >> 3) & 1;

    int acc[2][4][4];
    #pragma unroll
    for (int i = 0; i < 2; i++)
        #pragma unroll
        for (int j = 0; j < 4; j++)
            #pragma unroll
            for (int q = 0; q < 4; q++) acc[i][j][q] = 0;

    // prologue: chunks 0..2
    #pragma unroll
    for (int c = 0; c < 3; c++) {
        const uint32_t st = sb + (uint32_t)c * ST_BYTES;
        #pragma unroll
        for (int j = 0; j < 4; j++)
            cp16(st + sA[j], gA + (size_t)arow * K_DIM + c * KB + (aseg0 + j) * 16);
        #pragma unroll
        for (int j = 0; j < 2; j++)
            cp16(st + A_ST + sB[j], gB + (size_t)brow * K_DIM + c * KB + (bseg0 + j) * 16);
        cp_commit();
    }

    #pragma unroll 1
    for (int k = 0; k < NCHUNK; k++) {
        cp_wait2();
        __syncthreads();

        if (k + 3 < NCHUNK) {
            const uint32_t st = sb + (uint32_t)((k + 3) & 3) * ST_BYTES;
            #pragma unroll
            for (int j = 0; j < 4; j++)
                cp16(st + sA[j], gA + (size_t)arow * K_DIM + (k + 3) * KB + (aseg0 + j) * 16);
            #pragma unroll
            for (int j = 0; j < 2; j++)
                cp16(st + A_ST + sB[j], gB + (size_t)brow * K_DIM + (k + 3) * KB + (bseg0 + j) * 16);
        }
        cp_commit();

        const uint32_t Ast = sb + (uint32_t)(k & 3) * ST_BYTES;
        const uint32_t Bst = Ast + A_ST;

        #pragma unroll
        for (int ks = 0; ks < 4; ks++) {
            uint32_t af[2][4], bf[4][2];
            #pragma unroll
            for (int am = 0; am < 2; am++) {
                const uint32_t addr =
                    Ast + aRow128[am] + (uint32_t)((((ks << 1) + aKseg) ^ aMask[am]) << 4);
                LDSM_X4(af[am][0], af[am][1], af[am][2], af[am][3], addr);
            }
            #pragma unroll
            for (int bn = 0; bn < 4; bn++) {
                const uint32_t addr =
                    Bst + bRow128[bn] + (uint32_t)((((ks << 1) + bKseg) ^ bMask[bn]) << 4);
                LDSM_X2(bf[bn][0], bf[bn][1], addr);
            }
            #pragma unroll
            for (int am = 0; am < 2; am++)
                #pragma unroll
                for (int bn = 0; bn < 4; bn++)
                    IMMA(acc[am][bn], af[am], bf[bn]);
        }
    }

    const float mean = mean_g;
    const int g  = lane >> 2;
    const int c2 = (lane & 3) * 2;
    #pragma unroll
    for (int am = 0; am < 2; am++) {
        const int row0 = m0 + wm * 32 + am * 16 + g;
        #pragma unroll
        for (int bn = 0; bn < 4; bn++) {
            const int col = n0 + wn * 32 + bn * 8 + c2;
            const float2 bb = *(const float2*)(bias + col);
            float2 v0, v1;
            v0.x = ((float)acc[am][bn][0] + bb.x) * mean;
            v0.y = ((float)acc[am][bn][1] + bb.y) * mean;
            v1.x = ((float)acc[am][bn][2] + bb.x) * mean;
            v1.y = ((float)acc[am][bn][3] + bb.y) * mean;
            *(float2*)(out + (size_t)row0 * O_COLS + col) = v0;
            *(float2*)(out + (size_t)(row0 + 8) * O_COLS + col) = v1;
        }
    }
}

// ============================================================
// XNOR-popcount GEMM for rows [POPC_OFF, 8192): proven R8 config.
// ============================================================
#define BT 64
#define KW 16
#define KPAD 68

__global__ __launch_bounds__(256, 5)
void bgemm_kernel(const float* __restrict__ b, float* __restrict__ out) {
    __shared__ __align__(16) unsigned xs[KW][KPAD];
    __shared__ __align__(16) unsigned ws[KW][KPAD];

    const int tid = threadIdx.x;
    const int tx  = tid & 15;
    const int ty  = tid >> 4;
    const int o0  = blockIdx.x * BT;
    const int n0  = POPC_OFF + blockIdx.y * BT;

    const int lrow = tid >> 2;
    const int lq   = tid & 3;

    int sh;
    asm("mov.b32 %0, 0x10000;" : "=r"(sh));

    int accP[4][2];
    #pragma unroll
    for (int i = 0; i < 4; i++) { accP[i][0] = 0; accP[i][1] = 0; }

    for (int kw0 = 0; kw0 < KWORDS; kw0 += KW) {
        const uint4 xv = *(const uint4*)&xp_g[(size_t)(n0 + lrow) * KWORDS + kw0 + lq * 4];
        const uint4 wv = *(const uint4*)&wp_g[(size_t)(o0 + lrow) * KWORDS + kw0 + lq * 4];

        __syncthreads();
        xs[lq * 4 + 0][lrow] = xv.x;
        xs[lq * 4 + 1][lrow] = xv.y;
        xs[lq * 4 + 2][lrow] = xv.z;
        xs[lq * 4 + 3][lrow] = xv.w;
        ws[lq * 4 + 0][lrow] = wv.x;
        ws[lq * 4 + 1][lrow] = wv.y;
        ws[lq * 4 + 2][lrow] = wv.z;
        ws[lq * 4 + 3][lrow] = wv.w;
        __syncthreads();

        #pragma unroll
        for (int k = 0; k < KW; k += 2) {
            const uint4 a0 = *(const uint4*)&xs[k][ty * 4];
            const uint4 c0 = *(const uint4*)&ws[k][tx * 4];
            const uint4 a1 = *(const uint4*)&xs[k + 1][ty * 4];
            const uint4 c1 = *(const uint4*)&ws[k + 1][tx * 4];

            const unsigned ar0[4] = {a0.x, a0.y, a0.z, a0.w};
            const unsigned ar1[4] = {a1.x, a1.y, a1.z, a1.w};
            const unsigned cr0[4] = {c0.x, c0.y, c0.z, c0.w};
            const unsigned cr1[4] = {c1.x, c1.y, c1.z, c1.w};

            #pragma unroll
            for (int i = 0; i < 4; i++) {
                #pragma unroll
                for (int j2 = 0; j2 < 2; j2++) {
                    const int p0lo = __popc(ar0[i] ^ cr0[j2 * 2 + 0]);
                    const int p0hi = __popc(ar0[i] ^ cr0[j2 * 2 + 1]);
                    const int p1lo = __popc(ar1[i] ^ cr1[j2 * 2 + 0]);
                    const int p1hi = __popc(ar1[i] ^ cr1[j2 * 2 + 1]);
                    const int pc0 = imad_pack(p0hi, sh, p0lo);
                    const int pc1 = imad_pack(p1hi, sh, p1lo);
                    accP[i][j2] += pc0 + pc1;
                }
            }
        }
    }

    const float mean = mean_g;
    const int o_base = o0 + tx * 4;
    const int n_base = n0 + ty * 4;
    const float4 bb = *(const float4*)&b[o_base];

    #pragma unroll
    for (int i = 0; i < 4; i++) {
        const int c0 = accP[i][0] & 0xFFFF;
        const int c1 = (unsigned)accP[i][0] >> 16;
        const int c2 = accP[i][1] & 0xFFFF;
        const int c3 = (unsigned)accP[i][1] >> 16;
        float4 r;
        r.x = ((float)(K_DIM - 2 * c0) + bb.x) * mean;
        r.y = ((float)(K_DIM - 2 * c1) + bb.y) * mean;
        r.z = ((float)(K_DIM - 2 * c2) + bb.z) * mean;
        r.w = ((float)(K_DIM - 2 * c3) + bb.w) * mean;
        *(float4*)&out[(size_t)(n_base + i) * O_COLS + o_base] = r;
    }
}

// ============================================================
// launch: prep -> fork {IMMA rows [0,2944) || popc rows [2944,8192)} -> join
// Fork-join uses a side stream + events (canonical multi-branch capture).
// Streams/events are host-side objects (no device allocation); not destroyed
// mid-call because destroying a capture-participating stream before capture
// ends invalidates the graph. kernel_launch is called only a handful of times.
// ============================================================
extern "C" void kernel_launch(void* const* d_in, const int* in_sizes, int n_in,
                              void* d_out, int out_size) {
    const float* x = (const float*)d_in[0];   // [8192, 4096]
    const float* W = (const float*)d_in[1];   // [4096, 4096]
    const float* b = (const float*)d_in[2];   // [4096]
    float* out = (float*)d_out;

    cudaFuncSetAttribute(imma_gemm_kernel,
                         cudaFuncAttributeMaxDynamicSharedMemorySize, IM_SMEM);

    pack_x_kernel<<<N_ROWS, 128>>>(x);
    pack_w_kernel<<<O_COLS, 128>>>(W);
    reduce_mean_kernel<<<1, 1024>>>();

    cudaStream_t s2;
    cudaEvent_t ef, ej;
    cudaStreamCreateWithFlags(&s2, cudaStreamNonBlocking);
    cudaEventCreateWithFlags(&ef, cudaEventDisableTiming);
    cudaEventCreateWithFlags(&ej, cudaEventDisableTiming);

    cudaEventRecord(ef, 0);
    cudaStreamWaitEvent(s2, ef, 0);

    dim3 gi(O_COLS / IM_NT, IMMA_ROWS / IM_MT);        // (64, 23)
    imma_gemm_kernel<<<gi, 256, IM_SMEM, s2>>>(b, out);

    dim3 gp(O_COLS / BT, (N_ROWS - POPC_OFF) / BT);    // (64, 82)
    bgemm_kernel<<<gp, 256>>>(b, out);

    cudaEventRecord(ej, s2);
    cudaStreamWaitEvent(0, ej, 0);
}

// round 12
// speedup vs baseline: 1.3070x; 1.3070x over previous
#include <cuda_runtime.h>
#include <cstdint>

#define N_ROWS 8192
#define O_COLS 4096
#define K_DIM  4096
#define KWORDS 128          // K_DIM / 32

// ---- scratch (device globals; no dynamic allocation allowed) ----
__device__ __align__(16) unsigned xp_g[(size_t)N_ROWS * KWORDS];   // 4 MB
__device__ __align__(16) unsigned wp_g[(size_t)O_COLS * KWORDS];   // 2 MB
__device__ float psum_g[N_ROWS];
__device__ float mean_g;

// ============================================================
// Pack x rows into sign bits (bit=1 iff negative) + |x| row sums.
// ============================================================
__global__ void pack_x_kernel(const float* __restrict__ x) {
    const int row  = blockIdx.x;
    const int tid  = threadIdx.x;
    const int lane = tid & 31;
    const int warp = tid >> 5;

    const float* xr = x + (size_t)row * K_DIM;
    float s = 0.f;

    #pragma unroll 4
    for (int it = 0; it < 32; it++) {
        const int w = warp * 32 + it;
        const float v = xr[w * 32 + lane];
        s += fabsf(v);
        const unsigned bits = __ballot_sync(0xffffffffu, __float_as_uint(v) >> 31);
        if (lane == 0) xp_g[(size_t)row * KWORDS + w] = bits;
    }

    __shared__ float red[128];
    red[tid] = s;
    __syncthreads();
    #pragma unroll
    for (int off = 64; off > 0; off >>= 1) {
        if (tid < off) red[tid] += red[tid + off];
        __syncthreads();
    }
    if (tid == 0) psum_g[row] = red[0];
}

__global__ void pack_w_kernel(const float* __restrict__ W) {
    const int row  = blockIdx.x;
    const int tid  = threadIdx.x;
    const int lane = tid & 31;
    const int warp = tid >> 5;

    const float* wr = W + (size_t)row * K_DIM;

    #pragma unroll 4
    for (int it = 0; it < 32; it++) {
        const int w = warp * 32 + it;
        const float v = wr[w * 32 + lane];
        const unsigned bits = __ballot_sync(0xffffffffu, __float_as_uint(v) >> 31);
        if (lane == 0) wp_g[(size_t)row * KWORDS + w] = bits;
    }
}

__global__ void reduce_mean_kernel() {
    __shared__ float red[1024];
    const int tid = threadIdx.x;
    float s = 0.f;
    for (int i = tid; i < N_ROWS; i += 1024) s += psum_g[i];
    red[tid] = s;
    __syncthreads();
    #pragma unroll
    for (int off = 512; off > 0; off >>= 1) {
        if (tid < off) red[tid] += red[tid + off];
        __syncthreads();
    }
    if (tid == 0) mean_g = red[0] * (1.0f / ((float)N_ROWS * (float)K_DIM));
}

// ============================================================
// XNOR-popcount GEMM v4: barrier-free streaming.
// CTA tile 64(m) x 64(o), 256 threads, 4(m) x 4(o) per thread.
// Full-K W-bits tile (64 cols x 128 words = 34KB) loaded to smem ONCE,
// one __syncthreads, then zero syncs: A-bits stream via read-only LDG
// (L1-resident; 16 lanes share each address -> broadcast sectors),
// B via conflict-free LDS.128.
// dot = K - 2*count ; out = (dot + b) * mean
// ============================================================
#define BT 64
#define WPAD 68

__device__ __forceinline__ int imad_pack(int hi, int sh, int lo) {
    int r;
    asm("mad.lo.s32 %0, %1, %2, %3;" : "=r"(r) : "r"(hi), "r"(sh), "r"(lo));
    return r;
}

__global__ __launch_bounds__(256, 4)
void bgemm_kernel(const float* __restrict__ b, float* __restrict__ out) {
    // ws[k][c]: word k (0..127) of W row (o0+c), c = 0..63
    __shared__ __align__(16) unsigned ws[KWORDS][WPAD];

    const int tid = threadIdx.x;
    const int tx  = tid & 15;           // col group (4 cols)
    const int ty  = tid >> 4;           // row group (4 rows)
    const int o0  = blockIdx.x * BT;
    const int n0  = blockIdx.y * BT;

    // ---- one-time W tile load: thread covers col c, words kq*32..+31
    {
        const int c  = tid & 63;
        const int kq = tid >> 6;        // 0..3
        const uint4* gw = (const uint4*)(wp_g + (size_t)(o0 + c) * KWORDS + kq * 32);
        #pragma unroll
        for (int j = 0; j < 8; j++) {
            const uint4 v = __ldg(gw + j);
            ws[kq * 32 + j * 4 + 0][c] = v.x;
            ws[kq * 32 + j * 4 + 1][c] = v.y;
            ws[kq * 32 + j * 4 + 2][c] = v.z;
            ws[kq * 32 + j * 4 + 3][c] = v.w;
        }
    }
    __syncthreads();     // the ONLY barrier

    // per-thread A row pointers (uint4 granularity: 32 uint4 per row)
    const uint4* pa0 = (const uint4*)(xp_g + (size_t)(n0 + ty * 4 + 0) * KWORDS);
    const uint4* pa1 = (const uint4*)(xp_g + (size_t)(n0 + ty * 4 + 1) * KWORDS);
    const uint4* pa2 = (const uint4*)(xp_g + (size_t)(n0 + ty * 4 + 2) * KWORDS);
    const uint4* pa3 = (const uint4*)(xp_g + (size_t)(n0 + ty * 4 + 3) * KWORDS);

    int sh;   // 0x10000 in a register, opaque to constant folding
    asm("mov.b32 %0, 0x10000;" : "=r"(sh));

    // accP[i][j2]: lo16 = count(col tx*4 + 2*j2), hi16 = count(+1)
    int accP[4][2];
    #pragma unroll
    for (int i = 0; i < 4; i++) { accP[i][0] = 0; accP[i][1] = 0; }

    #pragma unroll 1
    for (int kk = 0; kk < 32; kk++) {           // 4 k-words per iteration
        const uint4 a0 = __ldg(pa0 + kk);
        const uint4 a1 = __ldg(pa1 + kk);
        const uint4 a2 = __ldg(pa2 + kk);
        const uint4 a3 = __ldg(pa3 + kk);
        const unsigned aw[4][4] = {
            {a0.x, a0.y, a0.z, a0.w},
            {a1.x, a1.y, a1.z, a1.w},
            {a2.x, a2.y, a2.z, a2.w},
            {a3.x, a3.y, a3.z, a3.w},
        };

        #pragma unroll
        for (int w = 0; w < 4; w++) {
            const uint4 bw = *(const uint4*)&ws[kk * 4 + w][tx * 4];
            #pragma unroll
            for (int i = 0; i < 4; i++) {
                const unsigned a = aw[i][w];
                const int p0 = __popc(a ^ bw.x);
                const int p1 = __popc(a ^ bw.y);
                const int p2 = __popc(a ^ bw.z);
                const int p3 = __popc(a ^ bw.w);
                accP[i][0] += imad_pack(p1, sh, p0);
                accP[i][1] += imad_pack(p3, sh, p2);
            }
        }
    }

    const float mean = mean_g;
    const int o_base = o0 + tx * 4;
    const int n_base = n0 + ty * 4;
    const float4 bb = *(const float4*)&b[o_base];

    #pragma unroll
    for (int i = 0; i < 4; i++) {
        const int c0 = accP[i][0] & 0xFFFF;
        const int c1 = (unsigned)accP[i][0] >> 16;
        const int c2 = accP[i][1] & 0xFFFF;
        const int c3 = (unsigned)accP[i][1] >> 16;
        float4 r;
        r.x = ((float)(K_DIM - 2 * c0) + bb.x) * mean;
        r.y = ((float)(K_DIM - 2 * c1) + bb.y) * mean;
        r.z = ((float)(K_DIM - 2 * c2) + bb.z) * mean;
        r.w = ((float)(K_DIM - 2 * c3) + bb.w) * mean;
        *(float4*)&out[(size_t)(n_base + i) * O_COLS + o_base] = r;
    }
}

// ============================================================
// launch: pack -> mean -> gemm (stream-ordered, graph-capturable)
// ============================================================
extern "C" void kernel_launch(void* const* d_in, const int* in_sizes, int n_in,
                              void* d_out, int out_size) {
    const float* x = (const float*)d_in[0];   // [8192, 4096]
    const float* W = (const float*)d_in[1];   // [4096, 4096]
    const float* b = (const float*)d_in[2];   // [4096]
    float* out = (float*)d_out;

    pack_x_kernel<<<N_ROWS, 128>>>(x);
    pack_w_kernel<<<O_COLS, 128>>>(W);
    reduce_mean_kernel<<<1, 1024>>>();

    dim3 grid(O_COLS / BT, N_ROWS / BT);      // (64, 128)
    bgemm_kernel<<<grid, 256>>>(b, out);
}